// round 3
// baseline (speedup 1.0000x reference)
#include <cuda_runtime.h>
#include <math.h>

#define DIM   1024
#define BLOCK 1024
#define NWARP (BLOCK / 32)              // 32 warps
#define GRID  128
#define ROWS_PER_CTA (DIM / GRID)       // 8
#define WARPS_PER_ROW 4                 // 4 warps split K per row

__device__ float        g_y[DIM];       // relu'd filter column, published once
__device__ float        g_z[DIM];       // highway outputs
__device__ unsigned int g_cnt_y = 0;    // y-publication counter
__device__ unsigned int g_cnt_z = 0;    // z-completion ticket

__global__ __launch_bounds__(BLOCK, 1)
void embed_fused_kernel(const float* __restrict__ filters,
                        const float* __restrict__ w_t,
                        const float* __restrict__ w_h,
                        float*       __restrict__ out,
                        int vocab)
{
    __shared__ float s_pt[NWARP];
    __shared__ float s_ph[NWARP];
    __shared__ float s_m[NWARP];
    __shared__ float s_s[NWARP];
    __shared__ float s_bc[2];
    __shared__ int   s_last;

    const int tid  = threadIdx.x;
    const int lane = tid & 31;
    const int warp = tid >> 5;

    const int row_local = warp >> 2;                 // 0..7
    const int kq        = warp & 3;                  // K-quarter
    const int row       = blockIdx.x * ROWS_PER_CTA + row_local;

    // ---- Publish this CTA's 8 filter elements (warp 0 only) -----------------
    if (warp == 0 && lane < ROWS_PER_CTA) {
        const int j = blockIdx.x * ROWS_PER_CTA + lane;
        float v = filters[(size_t)j * (size_t)vocab];
        v = (j == DIM - 1) ? v : fmaxf(v, 0.0f);
        __stcg(&g_y[j], v);
        __threadfence();                             // make store GPU-visible
    }
    if (warp == 0) {
        __syncwarp();
        if (lane == 0) atomicAdd(&g_cnt_y, 1u);
    }

    // ---- Issue the 8 MB weight stream NOW (overlaps the rendezvous) ---------
    const float4* __restrict__ wt4 = (const float4*)(w_t + (size_t)row * DIM);
    const float4* __restrict__ wh4 = (const float4*)(w_h + (size_t)row * DIM);
    const int i0 = kq * 64 + lane;
    const int i1 = i0 + 32;

    const float4 a0 = __ldcs(&wt4[i0]);
    const float4 a1 = __ldcs(&wt4[i1]);
    const float4 b0 = __ldcs(&wh4[i0]);
    const float4 b1 = __ldcs(&wh4[i1]);

    // ---- Wait until every CTA has published its slice of y ------------------
    if (tid == 0) {
        unsigned int c;
        do {
            asm volatile("ld.global.acquire.gpu.u32 %0, [%1];"
                         : "=r"(c) : "l"(&g_cnt_y) : "memory");
        } while (c < (unsigned int)GRID);
    }
    __syncthreads();

    // ---- Read full y coalesced from L2, do the dots --------------------------
    const float4* __restrict__ y4 = (const float4*)g_y;
    const float4 y0 = __ldcg(&y4[i0]);
    const float4 y1 = __ldcg(&y4[i1]);

    float dt = a0.x*y0.x + a0.y*y0.y + a0.z*y0.z + a0.w*y0.w
             + a1.x*y1.x + a1.y*y1.y + a1.z*y1.z + a1.w*y1.w;
    float dh = b0.x*y0.x + b0.y*y0.y + b0.z*y0.z + b0.w*y0.w
             + b1.x*y1.x + b1.y*y1.y + b1.z*y1.z + b1.w*y1.w;

    #pragma unroll
    for (int o = 16; o > 0; o >>= 1) {
        dt += __shfl_xor_sync(0xffffffffu, dt, o);
        dh += __shfl_xor_sync(0xffffffffu, dh, o);
    }
    if (lane == 0) { s_pt[warp] = dt; s_ph[warp] = dh; }
    __syncthreads();

    // ---- Gate and write z ----------------------------------------------------
    if (tid < ROWS_PER_CTA) {
        const int gr = blockIdx.x * ROWS_PER_CTA + tid;
        float ft = 0.0f, fh = 0.0f;
        #pragma unroll
        for (int w = 0; w < WARPS_PER_ROW; ++w) {
            ft += s_pt[tid * WARPS_PER_ROW + w];
            fh += s_ph[tid * WARPS_PER_ROW + w];
        }
        const float t = 1.0f / (1.0f + __expf(-ft));
        const float g = fmaxf(fh, 0.0f);
        const float yk = __ldca(&g_y[gr]);
        __stcg(&g_z[gr], t * g + (1.0f - t) * yk);
    }

    // ---- Last-CTA election ----------------------------------------------------
    __threadfence();
    __syncthreads();
    if (tid == 0) {
        unsigned int ticket = atomicAdd(&g_cnt_z, 1u);
        s_last = (ticket == (unsigned int)(GRID - 1));
    }
    __syncthreads();
    if (!s_last) return;

    // ---- log_softmax: merged online (max,sum) reduction -----------------------
    const float v = __ldcg(&g_z[tid]);

    float m = v, s = 1.0f;          // running (max, sum of exp(.-max))
    #pragma unroll
    for (int o = 16; o > 0; o >>= 1) {
        const float m2 = __shfl_xor_sync(0xffffffffu, m, o);
        const float s2 = __shfl_xor_sync(0xffffffffu, s, o);
        const float mn = fmaxf(m, m2);
        s = s * __expf(m - mn) + s2 * __expf(m2 - mn);
        m = mn;
    }
    if (lane == 0) { s_m[warp] = m; s_s[warp] = s; }
    __syncthreads();
    if (warp == 0) {
        float mm = s_m[lane];
        float ss = s_s[lane];
        #pragma unroll
        for (int o = 16; o > 0; o >>= 1) {
            const float m2 = __shfl_xor_sync(0xffffffffu, mm, o);
            const float s2 = __shfl_xor_sync(0xffffffffu, ss, o);
            const float mn = fmaxf(mm, m2);
            ss = ss * __expf(mm - mn) + s2 * __expf(m2 - mn);
            mm = mn;
        }
        if (lane == 0) { s_bc[0] = mm; s_bc[1] = ss; }
    }
    __syncthreads();

    out[tid] = v - s_bc[0] - __logf(s_bc[1]);

    // ---- Reset counters for the next graph replay ------------------------------
    if (tid == 0) { g_cnt_y = 0; g_cnt_z = 0; }
}

extern "C" void kernel_launch(void* const* d_in, const int* in_sizes, int n_in,
                              void* d_out, int out_size)
{
    const float* filters = (const float*)d_in[1];
    const float* w_t     = (const float*)d_in[2];
    const float* w_h     = (const float*)d_in[3];
    float*       out     = (float*)d_out;

    const int vocab = in_sizes[1] / DIM;   // 50257

    embed_fused_kernel<<<GRID, BLOCK>>>(filters, w_t, w_h, out, vocab);
}

// round 4
// speedup vs baseline: 1.1505x; 1.1505x over previous
#include <cuda_runtime.h>
#include <math.h>

#define DIM   1024
#define BLOCK 1024
#define NWARP (BLOCK / 32)              // 32 warps
#define GRID  128
#define ROWS_PER_CTA (DIM / GRID)       // 8
#define WARPS_PER_ROW 4                 // 4 warps split K per row

__device__ float        g_z[DIM];
__device__ unsigned int g_cnt = 0;

__global__ __launch_bounds__(BLOCK, 1)
void embed_fused_kernel(const float* __restrict__ filters,
                        const float* __restrict__ w_t,
                        const float* __restrict__ w_h,
                        float*       __restrict__ out,
                        int vocab)
{
    __shared__ float s_y[DIM];
    __shared__ float s_pt[NWARP];
    __shared__ float s_ph[NWARP];
    __shared__ float s_m[NWARP];
    __shared__ float s_s[NWARP];
    __shared__ float s_bc[2];
    __shared__ int   s_last;

    const int tid  = threadIdx.x;
    const int lane = tid & 31;
    const int warp = tid >> 5;

    const int row_local = warp >> 2;                 // 0..7
    const int kq        = warp & 3;                  // K-quarter
    const int row       = blockIdx.x * ROWS_PER_CTA + row_local;

    // ---- Weight stream first (plain loads: let L2 retain across replays) ----
    const float4* __restrict__ wt4 = (const float4*)(w_t + (size_t)row * DIM);
    const float4* __restrict__ wh4 = (const float4*)(w_h + (size_t)row * DIM);
    const int i0 = kq * 64 + lane;
    const int i1 = i0 + 32;

    const float4 a0 = wt4[i0];
    const float4 a1 = wt4[i1];
    const float4 b0 = wh4[i0];
    const float4 b1 = wh4[i1];

    // ---- Scattered filter gather (overlaps with stream) ---------------------
    {
        float v = filters[(size_t)tid * (size_t)vocab];
        s_y[tid] = (tid == DIM - 1) ? v : fmaxf(v, 0.0f);
    }
    __syncthreads();

    // ---- Dot products --------------------------------------------------------
    const float4* __restrict__ y4 = (const float4*)s_y;
    const float4 y0 = y4[i0];
    const float4 y1 = y4[i1];

    float dt = a0.x*y0.x + a0.y*y0.y + a0.z*y0.z + a0.w*y0.w
             + a1.x*y1.x + a1.y*y1.y + a1.z*y1.z + a1.w*y1.w;
    float dh = b0.x*y0.x + b0.y*y0.y + b0.z*y0.z + b0.w*y0.w
             + b1.x*y1.x + b1.y*y1.y + b1.z*y1.z + b1.w*y1.w;

    #pragma unroll
    for (int o = 16; o > 0; o >>= 1) {
        dt += __shfl_xor_sync(0xffffffffu, dt, o);
        dh += __shfl_xor_sync(0xffffffffu, dh, o);
    }
    if (lane == 0) { s_pt[warp] = dt; s_ph[warp] = dh; }
    __syncthreads();

    // ---- Gate and write z -----------------------------------------------------
    if (tid < ROWS_PER_CTA) {
        const int gr = blockIdx.x * ROWS_PER_CTA + tid;
        float ft = 0.0f, fh = 0.0f;
        #pragma unroll
        for (int w = 0; w < WARPS_PER_ROW; ++w) {
            ft += s_pt[tid * WARPS_PER_ROW + w];
            fh += s_ph[tid * WARPS_PER_ROW + w];
        }
        const float t = 1.0f / (1.0f + __expf(-ft));
        const float g = fmaxf(fh, 0.0f);
        g_z[gr] = t * g + (1.0f - t) * s_y[gr];
    }

    // ---- Arrival: ONE gpu-scope fence + ONE atomic per CTA ---------------------
    __syncthreads();                       // cta-scope hb: all z stores before tid0
    if (tid == 0) {
        __threadfence();                   // release: publish this CTA's z stores
        const unsigned int ticket = atomicAdd(&g_cnt, 1u);
        s_last = (ticket == (unsigned int)(GRID - 1));
        if (s_last) __threadfence();       // acquire side before reading others' z
    }
    __syncthreads();
    if (!s_last) return;

    // ---- log_softmax (last CTA): merged online (max,sum) reduction -------------
    const float v = __ldcg(&g_z[tid]);     // L2 read (L1 is flushed per launch)

    float m = v, s = 1.0f;
    #pragma unroll
    for (int o = 16; o > 0; o >>= 1) {
        const float m2 = __shfl_xor_sync(0xffffffffu, m, o);
        const float s2 = __shfl_xor_sync(0xffffffffu, s, o);
        const float mn = fmaxf(m, m2);
        s = s * __expf(m - mn) + s2 * __expf(m2 - mn);
        m = mn;
    }
    if (lane == 0) { s_m[warp] = m; s_s[warp] = s; }
    __syncthreads();
    if (warp == 0) {
        float mm = s_m[lane];
        float ss = s_s[lane];
        #pragma unroll
        for (int o = 16; o > 0; o >>= 1) {
            const float m2 = __shfl_xor_sync(0xffffffffu, mm, o);
            const float s2 = __shfl_xor_sync(0xffffffffu, ss, o);
            const float mn = fmaxf(mm, m2);
            ss = ss * __expf(mm - mn) + s2 * __expf(m2 - mn);
            mm = mn;
        }
        if (lane == 0) { s_bc[0] = mm; s_bc[1] = ss; }
    }
    __syncthreads();

    out[tid] = v - s_bc[0] - __logf(s_bc[1]);

    if (tid == 0) g_cnt = 0;               // deterministic across graph replays
}

extern "C" void kernel_launch(void* const* d_in, const int* in_sizes, int n_in,
                              void* d_out, int out_size)
{
    const float* filters = (const float*)d_in[1];
    const float* w_t     = (const float*)d_in[2];
    const float* w_h     = (const float*)d_in[3];
    float*       out     = (float*)d_out;

    const int vocab = in_sizes[1] / DIM;   // 50257

    embed_fused_kernel<<<GRID, BLOCK>>>(filters, w_t, w_h, out, vocab);
}